// round 16
// baseline (speedup 1.0000x reference)
#include <cuda_runtime.h>
#include <cstdint>

#define Nn 50000
#define Ee 500000
#define Rr 200
#define D  128
#define SLOPE 0.01f

// ---------------- device scratch ----------------
__device__ float g_Xa[Nn * D];
__device__ float g_Xb[Nn * D];
__device__ float g_Relc[Rr * D];
__device__ float g_sa[Nn];
__device__ float g_sb[Nn];
__device__ float g_sr[Rr];
__device__ float g_ex[Ee];      // leaky logits b
__device__ int   g_bmax[Nn];    // encoded float max
__device__ int   g_cnt[Nn];     // per-dst degree
__device__ int   g_off[Nn];     // CSR start
__device__ int   g_pos[Nn];     // fill cursor
__device__ int   g_cse[Ee];     // packed src | (et<<16), bucket order
__device__ float g_cb[Ee];      // b, bucket order

__device__ __forceinline__ int fenc(float f) {
    int i = __float_as_int(f);
    return (i >= 0) ? i : (i ^ 0x7FFFFFFF);
}
__device__ __forceinline__ float fdec(int i) {
    return __int_as_float((i >= 0) ? i : (i ^ 0x7FFFFFFF));
}

__device__ __forceinline__ uint32_t f2tf32(float f) {
    uint32_t r;
    asm("cvt.rna.tf32.f32 %0, %1;" : "=r"(r) : "f"(f));
    return r;
}

__device__ __forceinline__ void mma_tf32(float c[4], uint32_t a0, uint32_t a1,
                                         uint32_t a2, uint32_t a3,
                                         uint32_t b0, uint32_t b1) {
    asm volatile(
        "mma.sync.aligned.m16n8k8.row.col.f32.tf32.tf32.f32 "
        "{%0,%1,%2,%3},{%4,%5,%6,%7},{%8,%9},{%0,%1,%2,%3};"
        : "+f"(c[0]), "+f"(c[1]), "+f"(c[2]), "+f"(c[3])
        : "r"(a0), "r"(a1), "r"(a2), "r"(a3), "r"(b0), "r"(b1));
}

// ---------------- init ----------------
__global__ void init_kernel() {
    int i = blockIdx.x * blockDim.x + threadIdx.x;
    if (i < Nn) {
        g_bmax[i] = int(0x80000000);
        g_cnt[i]  = 0;
        g_sa[i]   = 0.0f;
        g_sb[i]   = 0.0f;
    }
}

// ---------------- GEMM (tf32): Xa / Xb = x @ W1[half] (+ b1) --------------
#define SA 36
#define SB 136
__global__ __launch_bounds__(256) void gemm_xab(const float* __restrict__ x,
                                                const float* __restrict__ W1,
                                                const float* __restrict__ b1,
                                                const float* __restrict__ w2) {
    __shared__ uint32_t As[128 * SA];
    __shared__ uint32_t Bs[32 * SB];

    const int half = blockIdx.y;
    const int rowBase = blockIdx.x * 128;
    const int tid  = threadIdx.x;
    const int lane = tid & 31;
    const int wid  = tid >> 5;
    const int gid  = lane >> 2;
    const int tig  = lane & 3;
    const int wy   = wid & 1;
    const int wx   = wid >> 1;
    const int m0w  = wy * 64;
    const int n0w  = wx * 32;

    float c[4][4][4];
#pragma unroll
    for (int i = 0; i < 4; i++)
#pragma unroll
        for (int j = 0; j < 4; j++)
#pragma unroll
            for (int r = 0; r < 4; r++) c[i][j][r] = 0.0f;

    const int am = tid >> 1;
    const int ac = (tid & 1) * 16;
    const int bk = tid >> 3;
    const int bc = (tid & 7) * 16;
    const float* Wbase = W1 + (size_t)half * 128 * 128;
    const bool arow_ok = (rowBase + am) < Nn;

    for (int k0 = 0; k0 < 128; k0 += 32) {
#pragma unroll
        for (int f = 0; f < 4; f++) {
            int col = ac + f * 4;
            float4 v = make_float4(0.f, 0.f, 0.f, 0.f);
            if (arow_ok)
                v = *(const float4*)(x + (size_t)(rowBase + am) * 128 + k0 + col);
            uint4 t = make_uint4(f2tf32(v.x), f2tf32(v.y), f2tf32(v.z), f2tf32(v.w));
            *(uint4*)&As[am * SA + col] = t;
        }
#pragma unroll
        for (int f = 0; f < 4; f++) {
            int col = bc + f * 4;
            float4 v = *(const float4*)(Wbase + (size_t)(k0 + bk) * 128 + col);
            uint4 t = make_uint4(f2tf32(v.x), f2tf32(v.y), f2tf32(v.z), f2tf32(v.w));
            *(uint4*)&Bs[bk * SB + col] = t;
        }
        __syncthreads();

#pragma unroll
        for (int ks = 0; ks < 4; ks++) {
            const int kk = ks * 8;
            uint32_t a[4][4];
#pragma unroll
            for (int i = 0; i < 4; i++) {
                int r0 = (m0w + i * 16 + gid) * SA + kk + tig;
                a[i][0] = As[r0];
                a[i][1] = As[r0 + 8 * SA];
                a[i][2] = As[r0 + 4];
                a[i][3] = As[r0 + 8 * SA + 4];
            }
#pragma unroll
            for (int jj = 0; jj < 4; jj++) {
                int bb = (kk + tig) * SB + n0w + jj * 8 + gid;
                uint32_t b0 = Bs[bb];
                uint32_t b1r = Bs[bb + 4 * SB];
#pragma unroll
                for (int i = 0; i < 4; i++)
                    mma_tf32(c[i][jj], a[i][0], a[i][1], a[i][2], a[i][3], b0, b1r);
            }
        }
        __syncthreads();
    }

    float* outp = half ? g_Xb : g_Xa;
    float* sp   = half ? g_sb : g_sa;
    float w2c[8], b1c[8];
#pragma unroll
    for (int j = 0; j < 8; j += 4) {
        *(float4*)&w2c[j] = *(const float4*)(w2 + ((lane & 3) * 2) * 4 + 0);
    }
    // reload cleanly (avoid aliasing confusion): per-column constants
#pragma unroll
    for (int i = 0; i < 4; i++) {
#pragma unroll
        for (int rh = 0; rh < 2; rh++) {
            int row = rowBase + m0w + i * 16 + rh * 8 + gid;
            float p = 0.f;
            if (row < Nn) {
#pragma unroll
                for (int jj = 0; jj < 4; jj++) {
                    int nb = n0w + jj * 8 + tig * 2;
                    float vx = c[i][jj][rh * 2];
                    float vy = c[i][jj][rh * 2 + 1];
                    if (half) { vx += b1[nb]; vy += b1[nb + 1]; }
                    p += vx * w2[nb] + vy * w2[nb + 1];
                    float2 st = make_float2(vx, vy);
                    *(float2*)&outp[(size_t)row * 128 + nb] = st;
                }
            }
            p += __shfl_xor_sync(0xFFFFFFFFu, p, 1);
            p += __shfl_xor_sync(0xFFFFFFFFu, p, 2);
            if (tig == 0 && row < Nn) atomicAdd(&sp[row], p);
        }
    }
}

// ---------------- Relc = rel @ W1c, sr = Relc . w2 ----------------
__global__ void relc_kernel(const float* __restrict__ rel,
                            const float* __restrict__ W1,
                            const float* __restrict__ w2) {
    const int r = blockIdx.x;
    const int j = threadIdx.x;
    __shared__ float rrow[128];
    __shared__ float red[128];
    rrow[j] = rel[(size_t)r * 128 + j];
    __syncthreads();
    const float* Wc = W1 + (size_t)256 * 128;
    float acc = 0.f;
#pragma unroll 8
    for (int k = 0; k < 128; k++) acc += rrow[k] * Wc[(size_t)k * 128 + j];
    g_Relc[(size_t)r * 128 + j] = acc;
    red[j] = acc * w2[j];
    __syncthreads();
    for (int s = 64; s > 0; s >>= 1) {
        if (j < s) red[j] += red[j + s];
        __syncthreads();
    }
    if (j == 0) g_sr[r] = red[0];
}

// ---------------- logits + segment max + dst histogram ---------------------
__global__ void logits_max(const int* __restrict__ src, const int* __restrict__ dst,
                           const int* __restrict__ et) {
    int q = blockIdx.x * blockDim.x + threadIdx.x;
    if (q >= Ee / 4) return;
    int4 s4 = ((const int4*)src)[q];
    int4 d4 = ((const int4*)dst)[q];
    int4 t4 = ((const int4*)et)[q];
    float b[4];
    {
        float v0 = g_sa[s4.x] + g_sb[d4.x] + g_sr[t4.x];
        float v1 = g_sa[s4.y] + g_sb[d4.y] + g_sr[t4.y];
        float v2 = g_sa[s4.z] + g_sb[d4.z] + g_sr[t4.z];
        float v3 = g_sa[s4.w] + g_sb[d4.w] + g_sr[t4.w];
        b[0] = (v0 > 0.f) ? v0 : SLOPE * v0;
        b[1] = (v1 > 0.f) ? v1 : SLOPE * v1;
        b[2] = (v2 > 0.f) ? v2 : SLOPE * v2;
        b[3] = (v3 > 0.f) ? v3 : SLOPE * v3;
    }
    ((float4*)g_ex)[q] = make_float4(b[0], b[1], b[2], b[3]);
    atomicMax(&g_bmax[d4.x], fenc(b[0]));
    atomicMax(&g_bmax[d4.y], fenc(b[1]));
    atomicMax(&g_bmax[d4.z], fenc(b[2]));
    atomicMax(&g_bmax[d4.w], fenc(b[3]));
    atomicAdd(&g_cnt[d4.x], 1);
    atomicAdd(&g_cnt[d4.y], 1);
    atomicAdd(&g_cnt[d4.z], 1);
    atomicAdd(&g_cnt[d4.w], 1);
}

// ---------------- exclusive scan of g_cnt -> g_off/g_pos (1 block) ---------
#define PER_T 49   // 1024*49 = 50176 >= Nn
__global__ __launch_bounds__(1024) void scan_kernel() {
    __shared__ int ps[1024];
    int t = threadIdx.x;
    int base = t * PER_T;
    int cnts[PER_T];
    int s = 0;
#pragma unroll
    for (int i = 0; i < PER_T; i++) {
        int idx = base + i;
        int c = (idx < Nn) ? g_cnt[idx] : 0;
        cnts[i] = c; s += c;
    }
    ps[t] = s;
    __syncthreads();
    for (int off = 1; off < 1024; off <<= 1) {
        int v = (t >= off) ? ps[t - off] : 0;
        __syncthreads();
        ps[t] += v;
        __syncthreads();
    }
    int run = ps[t] - s;   // exclusive prefix
#pragma unroll
    for (int i = 0; i < PER_T; i++) {
        int idx = base + i;
        if (idx < Nn) { g_off[idx] = run; g_pos[idx] = run; }
        run += cnts[i];
    }
}

// ---------------- fill CSR buckets ----------------
__global__ void fill_kernel(const int* __restrict__ src, const int* __restrict__ dst,
                            const int* __restrict__ et) {
    int e = blockIdx.x * blockDim.x + threadIdx.x;
    if (e >= Ee) return;
    int d = dst[e];
    int p = atomicAdd(&g_pos[d], 1);
    g_cse[p] = (src[e] & 0xFFFF) | (et[e] << 16);
    g_cb[p]  = g_ex[e];
}

// ---------------- gather: one warp per dst; softmax + weighted sum + out ---
__global__ __launch_bounds__(256) void gather_kernel(float* __restrict__ out) {
    int w = (blockIdx.x * blockDim.x + threadIdx.x) >> 5;
    int lane = threadIdx.x & 31;
    if (w >= Nn) return;
    int start = g_off[w], deg = g_cnt[w];
    if (deg == 0) {
        *(float4*)&out[(size_t)w * 128 + lane * 4] = make_float4(0.f, 0.f, 0.f, 0.f);
        return;
    }
    float m = fdec(g_bmax[w]);
    float denom = 0.f;
    float4 acc = make_float4(0.f, 0.f, 0.f, 0.f);
    for (int c0 = 0; c0 < deg; c0 += 32) {
        int i = c0 + lane;
        int pk = 0; float wv = 0.f;
        if (i < deg) {
            pk = g_cse[start + i];
            wv = expf(g_cb[start + i] - m);
        }
        denom += wv;
        int cnt = min(32, deg - c0);
        for (int j = 0; j < cnt; j++) {
            float wj = __shfl_sync(0xFFFFFFFFu, wv, j);
            int pkj  = __shfl_sync(0xFFFFFFFFu, pk, j);
            int s = pkj & 0xFFFF;
            int t = pkj >> 16;
            float4 xa = *(const float4*)&g_Xa[(size_t)s * 128 + lane * 4];
            float4 rc = *(const float4*)&g_Relc[(size_t)t * 128 + lane * 4];
            acc.x += wj * (xa.x + rc.x);
            acc.y += wj * (xa.y + rc.y);
            acc.z += wj * (xa.z + rc.z);
            acc.w += wj * (xa.w + rc.w);
        }
    }
#pragma unroll
    for (int o = 16; o > 0; o >>= 1) denom += __shfl_xor_sync(0xFFFFFFFFu, denom, o);
    float inv = 1.f / denom;
    float4 xb = *(const float4*)&g_Xb[(size_t)w * 128 + lane * 4];
    float4 o4;
    o4.x = acc.x * inv + xb.x; o4.x = (o4.x > 0.f) ? o4.x : SLOPE * o4.x;
    o4.y = acc.y * inv + xb.y; o4.y = (o4.y > 0.f) ? o4.y : SLOPE * o4.y;
    o4.z = acc.z * inv + xb.z; o4.z = (o4.z > 0.f) ? o4.z : SLOPE * o4.z;
    o4.w = acc.w * inv + xb.w; o4.w = (o4.w > 0.f) ? o4.w : SLOPE * o4.w;
    *(float4*)&out[(size_t)w * 128 + lane * 4] = o4;
}

// ---------------- host launcher ----------------
extern "C" void kernel_launch(void* const* d_in, const int* in_sizes, int n_in,
                              void* d_out, int out_size) {
    const float* x   = (const float*)d_in[0];
    const float* rel = (const float*)d_in[1];
    const float* W1  = (const float*)d_in[2];
    const float* b1  = (const float*)d_in[3];
    const float* w2  = (const float*)d_in[4];
    const int* eidx  = (const int*)d_in[5];
    const int* et    = (const int*)d_in[6];
    const int* src = eidx;
    const int* dst = eidx + Ee;
    float* out = (float*)d_out;

    init_kernel<<<(Nn + 255) / 256, 256>>>();
    gemm_xab<<<dim3((Nn + 127) / 128, 2), 256>>>(x, W1, b1, w2);
    relc_kernel<<<Rr, 128>>>(rel, W1, w2);
    logits_max<<<(Ee / 4 + 255) / 256, 256>>>(src, dst, et);
    scan_kernel<<<1, 1024>>>();
    fill_kernel<<<(Ee + 255) / 256, 256>>>(src, dst, et);
    gather_kernel<<<(Nn * 32 + 255) / 256, 256>>>(out);
}